// round 4
// baseline (speedup 1.0000x reference)
#include <cuda_runtime.h>
#include <cstdint>

// Equivariant linear: segments (u,i) = (64,1),(32,3),(16,5); in==out dim 240.
// K-pair trick: acc(v,r) += (x[u],x[u+1]) * (w[u][v],w[u+1][v]) via fma.rn.f32x2,
// horizontal lo+hi at the end. No operand-duplication movs anywhere in hot loops.

typedef unsigned long long u64;

__device__ __forceinline__ u64 fma2(u64 a, u64 b, u64 c) {
    u64 d;
    asm("fma.rn.f32x2 %0, %1, %2, %3;" : "=l"(d) : "l"(a), "l"(b), "l"(c));
    return d;
}
__device__ __forceinline__ float hsum2(u64 v) {
    float a, b;
    asm("mov.b64 {%0, %1}, %2;" : "=f"(a), "=f"(b) : "l"(v));
    return a + b;
}

// smem layout (floats):
//  sw1b  [0,     4096)  seg1 w blocks: (k4,t) -> 16 floats = 8 u64 pairs [j][vv]
//  sw2p  [4096,  5120)  seg2 w pairs:  idx=k*32+v -> (w[2k][v], w[2k+1][v])
//  sw3p  [5120,  5376)  seg3 w pairs:  idx=k*16+v
//  sx1   [5376,  7552)  32 rows x 68  (seg1 cols, row-major, padded)
//  sx23  [7552, 13312)  32 rows x 180 (seg2 i-major 96 + seg3 i-major 80, padded)
#define SMEM_FLOATS 13312
#define SX1_STRIDE 68
#define SX23_STRIDE 180

__global__ __launch_bounds__(128, 4) void eqlin_kernel(
    const float* __restrict__ x,
    const float* __restrict__ w,
    float* __restrict__ out,
    int n, int ntiles)
{
    extern __shared__ __align__(16) float smem[];
    float* sw1b = smem;
    float* sw2p = smem + 4096;
    float* sw3p = smem + 5120;
    float* sx1  = smem + 5376;
    float* sx23 = smem + 7552;

    const int tid = threadIdx.x;

    // ===================== build weight layouts ONCE per CTA =====================
    // seg1: blocks of 4u x 4v as u-pairs, scale 1/8
    #pragma unroll
    for (int b = tid; b < 256; b += 128) {
        int k4 = b >> 4, t = b & 15;
        float* dst = sw1b + b * 16;
        #pragma unroll
        for (int j = 0; j < 2; j++)
            #pragma unroll
            for (int vv = 0; vv < 4; vv++) {
                int u0 = 4 * k4 + 2 * j, col = 4 * t + vv;
                dst[(j * 4 + vv) * 2]     = w[u0 * 64 + col]       * 0.125f;
                dst[(j * 4 + vv) * 2 + 1] = w[(u0 + 1) * 64 + col] * 0.125f;
            }
    }
    // seg2: u-pairs, scale 1/sqrt(32)
    {
        const float* w2 = w + 4096;
        #pragma unroll
        for (int idx = tid; idx < 512; idx += 128) {
            int k = idx >> 5, v = idx & 31;
            sw2p[idx * 2]     = w2[(2 * k) * 32 + v]     * 0.17677669529663687f;
            sw2p[idx * 2 + 1] = w2[(2 * k + 1) * 32 + v] * 0.17677669529663687f;
        }
    }
    // seg3: u-pairs, scale 1/4
    {
        const float* w3 = w + 5120;
        int idx = tid;
        if (idx < 128) {
            int k = idx >> 4, v = idx & 15;
            sw3p[idx * 2]     = w3[(2 * k) * 16 + v]     * 0.25f;
            sw3p[idx * 2 + 1] = w3[(2 * k + 1) * 16 + v] * 0.25f;
        }
    }

    const int ty = tid >> 4;   // 0..7, 4 rows each
    const int tx = tid & 15;   // v-slice

    // ===================== persistent tile loop =====================
    for (int tile = blockIdx.x; tile < ntiles; tile += gridDim.x) {
        const long long rowbase = (long long)tile * 32;

        // ---- stage: coalesced LDG.128, scatter seg2/3 into i-major ----
        #pragma unroll
        for (int m = 0; m < 15; m++) {
            int fq = tid + m * 128;                // 0..1919
            int r = fq / 60, q = fq - r * 60;
            long long gr = rowbase + r;
            if (gr >= n) gr = n - 1;
            float4 v4 = *(const float4*)(x + gr * 240 + q * 4);
            if (q < 16) {
                *(float4*)(sx1 + r * SX1_STRIDE + q * 4) = v4;
            } else if (q < 40) {
                int j0 = q * 4 - 64;               // 0..95, j = 3u+i
                float vals[4] = {v4.x, v4.y, v4.z, v4.w};
                #pragma unroll
                for (int e = 0; e < 4; e++) {
                    int j = j0 + e, u = j / 3, i = j - u * 3;
                    sx23[r * SX23_STRIDE + i * 32 + u] = vals[e];
                }
            } else {
                int j0 = q * 4 - 160;              // 0..79, j = 5u+i
                float vals[4] = {v4.x, v4.y, v4.z, v4.w};
                #pragma unroll
                for (int e = 0; e < 4; e++) {
                    int j = j0 + e, u = j / 5, i = j - u * 5;
                    sx23[r * SX23_STRIDE + 96 + i * 16 + u] = vals[e];
                }
            }
        }
        __syncthreads();

        const float* xr1[4];
        const float* xr23[4];
        long long gr[4]; bool pr[4];
        #pragma unroll
        for (int r = 0; r < 4; r++) {
            int row = 4 * ty + r;
            gr[r] = rowbase + row;
            pr[r] = gr[r] < n;
            xr1[r]  = sx1  + row * SX1_STRIDE;
            xr23[r] = sx23 + row * SX23_STRIDE;
        }

        // =============== Segment 1: u=v=64, i=1, v = 4tx..4tx+3 ===============
        {
            u64 acc[4][4];   // [vv][r]
            #pragma unroll
            for (int vv = 0; vv < 4; vv++)
                #pragma unroll
                for (int r = 0; r < 4; r++) acc[vv][r] = 0ull;

            #pragma unroll 4
            for (int k4 = 0; k4 < 16; k4++) {
                const ulonglong2* wb = (const ulonglong2*)(sw1b + (k4 * 16 + tx) * 16);
                ulonglong2 wa = wb[0];   // j=0: vv0, vv1
                ulonglong2 wc = wb[1];   // j=0: vv2, vv3
                ulonglong2 wd = wb[2];   // j=1: vv0, vv1
                ulonglong2 we = wb[3];   // j=1: vv2, vv3
                #pragma unroll
                for (int r = 0; r < 4; r++) {
                    ulonglong2 xq = *(const ulonglong2*)(xr1[r] + 4 * k4);
                    acc[0][r] = fma2(xq.y, wd.x, fma2(xq.x, wa.x, acc[0][r]));
                    acc[1][r] = fma2(xq.y, wd.y, fma2(xq.x, wa.y, acc[1][r]));
                    acc[2][r] = fma2(xq.y, we.x, fma2(xq.x, wc.x, acc[2][r]));
                    acc[3][r] = fma2(xq.y, we.y, fma2(xq.x, wc.y, acc[3][r]));
                }
            }
            #pragma unroll
            for (int r = 0; r < 4; r++) {
                if (!pr[r]) continue;
                float4 o;
                o.x = hsum2(acc[0][r]); o.y = hsum2(acc[1][r]);
                o.z = hsum2(acc[2][r]); o.w = hsum2(acc[3][r]);
                *(float4*)(out + gr[r] * 240 + 4 * tx) = o;
            }
        }

        // =============== Segment 2: u=v=32, i=3, v = 2tx, 2tx+1 ===============
        {
            u64 acc[2][3][4];  // [vl][i][r]
            #pragma unroll
            for (int vl = 0; vl < 2; vl++)
                #pragma unroll
                for (int i = 0; i < 3; i++)
                    #pragma unroll
                    for (int r = 0; r < 4; r++) acc[vl][i][r] = 0ull;

            #pragma unroll 2
            for (int k4 = 0; k4 < 8; k4++) {
                ulonglong2 wA = *(const ulonglong2*)(sw2p + ((2 * k4) * 32 + 2 * tx) * 2);
                ulonglong2 wB = *(const ulonglong2*)(sw2p + ((2 * k4 + 1) * 32 + 2 * tx) * 2);
                #pragma unroll
                for (int r = 0; r < 4; r++)
                    #pragma unroll
                    for (int i = 0; i < 3; i++) {
                        ulonglong2 xq = *(const ulonglong2*)(xr23[r] + i * 32 + 4 * k4);
                        acc[0][i][r] = fma2(xq.y, wB.x, fma2(xq.x, wA.x, acc[0][i][r]));
                        acc[1][i][r] = fma2(xq.y, wB.y, fma2(xq.x, wA.y, acc[1][i][r]));
                    }
            }
            #pragma unroll
            for (int r = 0; r < 4; r++) {
                if (!pr[r]) continue;
                float* p = out + gr[r] * 240 + 64 + 6 * tx;
                *(float2*)(p)     = make_float2(hsum2(acc[0][0][r]), hsum2(acc[0][1][r]));
                *(float2*)(p + 2) = make_float2(hsum2(acc[0][2][r]), hsum2(acc[1][0][r]));
                *(float2*)(p + 4) = make_float2(hsum2(acc[1][1][r]), hsum2(acc[1][2][r]));
            }
        }

        // =============== Segment 3: u=v=16, i=5, v = tx ===============
        {
            u64 acc[5][4];   // [i][r]
            #pragma unroll
            for (int i = 0; i < 5; i++)
                #pragma unroll
                for (int r = 0; r < 4; r++) acc[i][r] = 0ull;

            #pragma unroll
            for (int k4 = 0; k4 < 4; k4++) {
                u64 wA = *(const u64*)(sw3p + ((2 * k4) * 16 + tx) * 2);
                u64 wB = *(const u64*)(sw3p + ((2 * k4 + 1) * 16 + tx) * 2);
                #pragma unroll
                for (int r = 0; r < 4; r++)
                    #pragma unroll
                    for (int i = 0; i < 5; i++) {
                        ulonglong2 xq = *(const ulonglong2*)(xr23[r] + 96 + i * 16 + 4 * k4);
                        acc[i][r] = fma2(xq.y, wB, fma2(xq.x, wA, acc[i][r]));
                    }
            }
            #pragma unroll
            for (int r = 0; r < 4; r++) {
                if (!pr[r]) continue;
                float* p = out + gr[r] * 240 + 160 + 5 * tx;
                p[0] = hsum2(acc[0][r]);
                p[1] = hsum2(acc[1][r]);
                p[2] = hsum2(acc[2][r]);
                p[3] = hsum2(acc[3][r]);
                p[4] = hsum2(acc[4][r]);
            }
        }

        __syncthreads();   // smem x tiles reused next iteration
    }
}

extern "C" void kernel_launch(void* const* d_in, const int* in_sizes, int n_in,
                              void* d_out, int out_size) {
    const float* x = (const float*)d_in[0];
    const float* w = (const float*)d_in[1];
    float* out = (float*)d_out;
    const int n = in_sizes[0] / 240;            // 200000
    const int ntiles = (n + 31) / 32;           // 6250
    const int smem_bytes = SMEM_FLOATS * 4;     // 53248

    static int grid = 0;
    if (!grid) {
        int dev = 0, sms = 148;
        cudaGetDevice(&dev);
        cudaDeviceGetAttribute(&sms, cudaDevAttrMultiProcessorCount, dev);
        grid = sms * 4;
        cudaFuncSetAttribute(eqlin_kernel,
                             cudaFuncAttributeMaxDynamicSharedMemorySize, smem_bytes);
    }
    int g = grid < ntiles ? grid : ntiles;
    eqlin_kernel<<<g, 128, smem_bytes>>>(x, w, out, n, ntiles);
}

// round 5
// speedup vs baseline: 2.0453x; 2.0453x over previous
#include <cuda_runtime.h>
#include <cstdint>

// Equivariant linear: segments (u,i) = (64,1),(32,3),(16,5); in==out dim 240.
// Balanced warp tiles: seg1 16r x 32v (K-pair fma2, no dups),
// seg2 16r x 16v, seg3 8r x 16v (v-pair fma2, dup'd x).

typedef unsigned long long u64;

__device__ __forceinline__ u64 fma2(u64 a, u64 b, u64 c) {
    u64 d;
    asm("fma.rn.f32x2 %0, %1, %2, %3;" : "=l"(d) : "l"(a), "l"(b), "l"(c));
    return d;
}
__device__ __forceinline__ u64 dup2(float x) {
    u64 d;
    asm("mov.b64 %0, {%1, %2};" : "=l"(d) : "f"(x), "f"(x));
    return d;
}
__device__ __forceinline__ float hsum2(u64 v) {
    float a, b;
    asm("mov.b64 {%0, %1}, %2;" : "=f"(a), "=f"(b) : "l"(v));
    return a + b;
}
__device__ __forceinline__ void unpack2(u64 v, float& a, float& b) {
    asm("mov.b64 {%0, %1}, %2;" : "=f"(a), "=f"(b) : "l"(v));
}
__device__ __forceinline__ uint32_t s2u(const void* p) {
    uint32_t a;
    asm("{ .reg .u64 t; cvta.to.shared.u64 t, %1; cvt.u32.u64 %0, t; }"
        : "=r"(a) : "l"(p));
    return a;
}
__device__ __forceinline__ void mbar_wait(uint32_t mbar, uint32_t parity) {
    asm volatile(
        "{\n\t.reg .pred P;\n\t"
        "W%=:\n\t"
        "mbarrier.try_wait.parity.acquire.cta.shared::cta.b64 P, [%0], %1;\n\t"
        "@P bra.uni D%=;\n\t"
        "bra.uni W%=;\n\t"
        "D%=:\n\t}"
        :: "r"(mbar), "r"(parity) : "memory");
}

// smem layout (float offsets)
#define SW1_OFF 0       // 128 blocks x 36 floats (18 u64, 16 used) = 4608
#define SW2_OFF 4608    // 1024 floats (512 u64 v-pairs, row-major copy)
#define SW3_OFF 5632    // 256 floats (128 u64 v-pairs)
#define SX_OFF  5888    // 64 rows x 248 floats
#define XSTRIDE 248
#define MB_OFF  (5888 + 64 * 248)          // 21760
#define SMEM_FLOATS (MB_OFF + 4)           // 21764 -> 87056 B

__global__ __launch_bounds__(256, 2) void eqlin_kernel(
    const float* __restrict__ x,
    const float* __restrict__ w,
    float* __restrict__ out,
    int n, int ntiles)
{
    extern __shared__ __align__(16) float sm[];
    float* sW1 = sm + SW1_OFF;
    float* sW2 = sm + SW2_OFF;
    float* sW3 = sm + SW3_OFF;
    float* sX  = sm + SX_OFF;
    const uint32_t mbar = s2u(sm + MB_OFF);

    const int tid = threadIdx.x;

    // ======== build weights ONCE (persistent CTA) ========
    // seg1: block b=(k4*2+vh)*4+lb, 36-float stride (conflict-free: 9 mod 8 groups)
    // block content: u64 pair P[j][vv] = (w[4k4+2j][v], w[4k4+2j+1][v]), v=32vh+8lb+vv
    if (tid < 128) {
        int k4 = tid >> 3, vh = (tid >> 2) & 1, lb = tid & 3;
        float* blk = sW1 + tid * 36;
        #pragma unroll
        for (int j = 0; j < 2; j++)
            #pragma unroll
            for (int vv = 0; vv < 8; vv++) {
                int v = 32 * vh + 8 * lb + vv;
                int u0 = 4 * k4 + 2 * j;
                blk[(j * 8 + vv) * 2]     = w[u0 * 64 + v]       * 0.125f;
                blk[(j * 8 + vv) * 2 + 1] = w[(u0 + 1) * 64 + v] * 0.125f;
            }
    }
    // seg2/seg3: scaled row-major copies (u64 view = natural (v,v+1) pairs)
    #pragma unroll
    for (int i = tid; i < 1024; i += 256)
        sW2[i] = w[4096 + i] * 0.17677669529663687f;
    if (tid < 256)
        sW3[tid] = w[5120 + tid] * 0.25f;
    if (tid == 0)
        asm volatile("mbarrier.init.shared.b64 [%0], 1;" :: "r"(mbar) : "memory");
    __syncthreads();

    const int warp = tid >> 5, lane = tid & 31;
    const int la = lane >> 2, lb = lane & 3;    // la: row selector, lb: v selector
    const int wy = warp >> 1, wx = warp & 1;

    uint32_t parity = 0;

    for (int tile = blockIdx.x; tile < ntiles; tile += gridDim.x) {
        const long long base = (long long)tile * 64;
        int rows = (int)(n - base);
        if (rows > 64) rows = 64;

        // ---- TMA in: 64 per-row bulk copies into the strided tile ----
        if (tid == 0)
            asm volatile("mbarrier.arrive.expect_tx.shared.b64 _, [%0], %1;"
                         :: "r"(mbar), "r"((uint32_t)rows * 960u) : "memory");
        if (tid < rows)
            asm volatile(
                "cp.async.bulk.shared::cta.global.mbarrier::complete_tx::bytes "
                "[%0], [%1], 960, [%2];"
                :: "r"(s2u(sX + tid * XSTRIDE)),
                   "l"(x + (base + tid) * 240), "r"(mbar)
                : "memory");
        mbar_wait(mbar, parity);
        parity ^= 1;

        // ================= Segment 1: 16r x 32v per warp, K-pair =================
        {
            const int r0 = 16 * wy + 2 * la;
            const float* xb0 = sX + r0 * XSTRIDE;
            const float* xb1 = xb0 + XSTRIDE;
            u64 acc[2][8];
            #pragma unroll
            for (int rr = 0; rr < 2; rr++)
                #pragma unroll
                for (int vv = 0; vv < 8; vv++) acc[rr][vv] = 0ull;

            #pragma unroll 2
            for (int k4 = 0; k4 < 16; k4++) {
                const ulonglong2* W =
                    (const ulonglong2*)(sW1 + (k4 * 8 + wx * 4 + lb) * 36);
                u64 wj0[8], wj1[8];
                #pragma unroll
                for (int q = 0; q < 4; q++) {
                    ulonglong2 t0 = W[q];     // j=0, vv 2q,2q+1
                    ulonglong2 t1 = W[q + 4]; // j=1
                    wj0[2 * q] = t0.x; wj0[2 * q + 1] = t0.y;
                    wj1[2 * q] = t1.x; wj1[2 * q + 1] = t1.y;
                }
                ulonglong2 xq0 = *(const ulonglong2*)(xb0 + 4 * k4);
                ulonglong2 xq1 = *(const ulonglong2*)(xb1 + 4 * k4);
                #pragma unroll
                for (int vv = 0; vv < 8; vv++) {
                    acc[0][vv] = fma2(xq0.y, wj1[vv], fma2(xq0.x, wj0[vv], acc[0][vv]));
                    acc[1][vv] = fma2(xq1.y, wj1[vv], fma2(xq1.x, wj0[vv], acc[1][vv]));
                }
            }
            #pragma unroll
            for (int rr = 0; rr < 2; rr++) {
                if (r0 + rr >= rows) continue;
                float o[8];
                #pragma unroll
                for (int vv = 0; vv < 8; vv++) o[vv] = hsum2(acc[rr][vv]);
                float* p = out + (base + r0 + rr) * 240 + 32 * wx + 8 * lb;
                *(float4*)(p)     = make_float4(o[0], o[1], o[2], o[3]);
                *(float4*)(p + 4) = make_float4(o[4], o[5], o[6], o[7]);
            }
        }

        // ================= Segment 2: 16r x 16v per warp, v-pair =================
        {
            const int r0 = 16 * wy + 2 * la;
            const float* xb0 = sX + r0 * XSTRIDE + 64;
            const float* xb1 = xb0 + XSTRIDE;
            const int vp0 = 8 * wx + 2 * lb;       // first of 2 v-pairs
            u64 acc[2][2][3];
            #pragma unroll
            for (int rr = 0; rr < 2; rr++)
                #pragma unroll
                for (int vp = 0; vp < 2; vp++)
                    #pragma unroll
                    for (int i = 0; i < 3; i++) acc[rr][vp][i] = 0ull;

            #pragma unroll 2
            for (int k4 = 0; k4 < 8; k4++) {
                ulonglong2 Wu[4];
                #pragma unroll
                for (int u = 0; u < 4; u++)
                    Wu[u] = *(const ulonglong2*)(sW2 + ((4 * k4 + u) * 16 + vp0) * 2);
                #pragma unroll
                for (int rr = 0; rr < 2; rr++) {
                    const float* xb = rr ? xb1 : xb0;
                    float4 xa = *(const float4*)(xb + 12 * k4);
                    float4 xm = *(const float4*)(xb + 12 * k4 + 4);
                    float4 xc = *(const float4*)(xb + 12 * k4 + 8);
                    float xf[12] = {xa.x, xa.y, xa.z, xa.w, xm.x, xm.y,
                                    xm.z, xm.w, xc.x, xc.y, xc.z, xc.w};
                    #pragma unroll
                    for (int u = 0; u < 4; u++)
                        #pragma unroll
                        for (int i = 0; i < 3; i++) {
                            u64 d = dup2(xf[3 * u + i]);
                            acc[rr][0][i] = fma2(d, Wu[u].x, acc[rr][0][i]);
                            acc[rr][1][i] = fma2(d, Wu[u].y, acc[rr][1][i]);
                        }
                }
            }
            #pragma unroll
            for (int rr = 0; rr < 2; rr++) {
                if (r0 + rr >= rows) continue;
                float f[12];
                #pragma unroll
                for (int vp = 0; vp < 2; vp++)
                    #pragma unroll
                    for (int i = 0; i < 3; i++) {
                        float lo, hi;
                        unpack2(acc[rr][vp][i], lo, hi);
                        f[6 * vp + i]     = lo;
                        f[6 * vp + 3 + i] = hi;
                    }
                float* p = out + (base + r0 + rr) * 240 + 64 + 48 * wx + 12 * lb;
                *(float4*)(p)     = make_float4(f[0], f[1], f[2],  f[3]);
                *(float4*)(p + 4) = make_float4(f[4], f[5], f[6],  f[7]);
                *(float4*)(p + 8) = make_float4(f[8], f[9], f[10], f[11]);
            }
        }

        // ================= Segment 3: 8r x 16v per warp, v-pair =================
        {
            const int row = 8 * warp + la;
            const float* xb = sX + row * XSTRIDE + 160;
            const int vp0 = 2 * lb;                // first of 2 v-pairs
            u64 acc[2][5];
            #pragma unroll
            for (int vp = 0; vp < 2; vp++)
                #pragma unroll
                for (int i = 0; i < 5; i++) acc[vp][i] = 0ull;

            #pragma unroll
            for (int k4 = 0; k4 < 4; k4++) {
                ulonglong2 Wu[4];
                #pragma unroll
                for (int u = 0; u < 4; u++)
                    Wu[u] = *(const ulonglong2*)(sW3 + ((4 * k4 + u) * 8 + vp0) * 2);
                float4 x0 = *(const float4*)(xb + 20 * k4);
                float4 x1 = *(const float4*)(xb + 20 * k4 + 4);
                float4 x2 = *(const float4*)(xb + 20 * k4 + 8);
                float4 x3 = *(const float4*)(xb + 20 * k4 + 12);
                float4 x4 = *(const float4*)(xb + 20 * k4 + 16);
                float xf[20] = {x0.x, x0.y, x0.z, x0.w, x1.x, x1.y, x1.z, x1.w,
                                x2.x, x2.y, x2.z, x2.w, x3.x, x3.y, x3.z, x3.w,
                                x4.x, x4.y, x4.z, x4.w};
                #pragma unroll
                for (int u = 0; u < 4; u++)
                    #pragma unroll
                    for (int i = 0; i < 5; i++) {
                        u64 d = dup2(xf[5 * u + i]);
                        acc[0][i] = fma2(d, Wu[u].x, acc[0][i]);
                        acc[1][i] = fma2(d, Wu[u].y, acc[1][i]);
                    }
            }
            if (row < rows) {
                float f[20];
                #pragma unroll
                for (int vp = 0; vp < 2; vp++)
                    #pragma unroll
                    for (int i = 0; i < 5; i++) {
                        float lo, hi;
                        unpack2(acc[vp][i], lo, hi);
                        f[5 * (2 * vp) + i]     = lo;
                        f[5 * (2 * vp + 1) + i] = hi;
                    }
                float* p = out + (base + row) * 240 + 160 + 20 * lb;
                *(float4*)(p)      = make_float4(f[0],  f[1],  f[2],  f[3]);
                *(float4*)(p + 4)  = make_float4(f[4],  f[5],  f[6],  f[7]);
                *(float4*)(p + 8)  = make_float4(f[8],  f[9],  f[10], f[11]);
                *(float4*)(p + 12) = make_float4(f[12], f[13], f[14], f[15]);
                *(float4*)(p + 16) = make_float4(f[16], f[17], f[18], f[19]);
            }
        }

        __syncthreads();   // all smem reads done before next tile's TMA overwrite
    }
}

extern "C" void kernel_launch(void* const* d_in, const int* in_sizes, int n_in,
                              void* d_out, int out_size) {
    const float* x = (const float*)d_in[0];
    const float* w = (const float*)d_in[1];
    float* out = (float*)d_out;
    const int n = in_sizes[0] / 240;            // 200000
    const int ntiles = (n + 63) / 64;           // 3125 (exact)
    const int smem_bytes = SMEM_FLOATS * 4;     // 87056

    static int grid = 0;
    if (!grid) {
        int dev = 0, sms = 148;
        cudaGetDevice(&dev);
        cudaDeviceGetAttribute(&sms, cudaDevAttrMultiProcessorCount, dev);
        grid = sms * 2;                          // 2 CTAs resident per SM
        cudaFuncSetAttribute(eqlin_kernel,
                             cudaFuncAttributeMaxDynamicSharedMemorySize, smem_bytes);
    }
    int g = grid < ntiles ? grid : ntiles;
    eqlin_kernel<<<g, 256, smem_bytes>>>(x, w, out, n, ntiles);
}